// round 2
// baseline (speedup 1.0000x reference)
#include <cuda_runtime.h>
#include <math.h>

#define Bn 16
#define Ln 2048
#define Mn 32000
#define Dn 512
#define NCHUNK 16           // chunks per batch in k24 (128 tokens each)
#define NIPB   1000         // k_ip blocks (32 tokens each)

// ---------------- scratch ----------------
__device__ float g_inv_e[Mn + 1];
__device__ float g_inv_p[Ln];
__device__ float g_partial[Bn * NCHUNK * Dn];
__device__ float g_wpart[Bn * NCHUNK];
__device__ float g_sel[Bn * Dn];
__device__ float g_esum[Bn * NIPB];
__device__ float g_tgtip[Bn];

__device__ __forceinline__ float dot4(float4 a, float4 b) {
    return a.x * b.x + a.y * b.y + a.z * b.z + a.w * b.w;
}

// ---------------- K1: row inverse norms for emb AND pos (warp/row) -------
__global__ void k_norms(const float* __restrict__ emb,
                        const float* __restrict__ pos) {
    int warp = (blockIdx.x * blockDim.x + threadIdx.x) >> 5;
    int lane = threadIdx.x & 31;
    int total = (Mn + 1) + Ln;
    if (warp >= total) return;
    const float* r = (warp <= Mn) ? emb + (size_t)warp * Dn
                                  : pos + (size_t)(warp - (Mn + 1)) * Dn;
    const float4* r4 = (const float4*)r;
    float s = 0.f;
#pragma unroll
    for (int j = 0; j < 4; j++) { float4 v = r4[lane + 32 * j]; s += dot4(v, v); }
#pragma unroll
    for (int o = 16; o; o >>= 1) s += __shfl_xor_sync(0xffffffffu, s, o);
    if (lane == 0) {
        float inv = 1.0f / fmaxf(sqrtf(s), 1.0f);
        if (warp <= Mn) g_inv_e[warp] = inv; else g_inv_p[warp - (Mn + 1)] = inv;
    }
}

// ---------------- K2: fused logits + exp + weighted gather-sum -----------
// grid (NCHUNK, Bn), block 512. Chunk = 128 tokens.
__global__ __launch_bounds__(512) void k24(
    const float* __restrict__ emb, const float* __restrict__ pos,
    const int* __restrict__ x, const int* __restrict__ mask_idx) {
    __shared__ __align__(16) float qs[Dn];
    __shared__ __align__(16) float ps[Dn];
    __shared__ float wsh[128];   // exp(logit)*inv_e[tok]
    __shared__ float esh[128];   // exp(logit)
    __shared__ int   tsh[128];
    int b = blockIdx.y, c = blockIdx.x;
    int tid = threadIdx.x;
    int mb = mask_idx[b];
    float ie_m = g_inv_e[Mn];
    float ip_mb = g_inv_p[mb];
    qs[tid] = emb[(size_t)Mn * Dn + tid] * ie_m;
    ps[tid] = pos[(size_t)mb * Dn + tid] * ip_mb;
    __syncthreads();

    int wid = tid >> 5, lane = tid & 31;
    const float4* q4 = (const float4*)qs;
    const float4* p4 = (const float4*)ps;
#pragma unroll 1
    for (int k = 0; k < 8; k++) {
        int i = wid * 8 + k;            // 0..127 in chunk
        int m = c * 128 + i;
        int tok = (m == mb) ? Mn : x[b * Ln + m];
        const float4* er = (const float4*)(emb + (size_t)tok * Dn);
        const float4* pr = (const float4*)(pos + (size_t)m * Dn);
        float dc = 0.f, dp = 0.f;
#pragma unroll
        for (int j = 0; j < 4; j++) {
            dc += dot4(er[lane + 32 * j], q4[lane + 32 * j]);
            dp += dot4(pr[lane + 32 * j], p4[lane + 32 * j]);
        }
        float inve = g_inv_e[tok];
        float s = dc * inve + dp * g_inv_p[m];
#pragma unroll
        for (int o = 16; o; o >>= 1) s += __shfl_xor_sync(0xffffffffu, s, o);
        if (lane == 0) {
            float e = __expf(s * (1.0f / 32.0f));
            esh[i] = e;
            wsh[i] = e * inve;
            tsh[i] = tok;
        }
    }
    __syncthreads();
    // partial sum of exp over this chunk (fixed-order, deterministic)
    if (tid < 32) {
        float sw = esh[tid] + esh[tid + 32] + esh[tid + 64] + esh[tid + 96];
#pragma unroll
        for (int o = 16; o; o >>= 1) sw += __shfl_xor_sync(0xffffffffu, sw, o);
        if (tid == 0) g_wpart[b * NCHUNK + c] = sw;
    }
    // weighted sum over chunk: thread = d; rows are hot in L2/L1
    float acc = 0.f;
    int d = tid;
#pragma unroll 4
    for (int i = 0; i < 128; i++)
        acc += emb[(size_t)tsh[i] * Dn + d] * wsh[i];
    g_partial[(b * NCHUNK + c) * Dn + d] = acc;
}

// ---------------- K3: reduce partials, normalize -> sel ----------------
__global__ __launch_bounds__(512) void k_sel(float* __restrict__ out_sel) {
    int b = blockIdx.x, tid = threadIdx.x;
    __shared__ float sinv;
    if (tid < 32) {
        float v = (tid < NCHUNK) ? g_wpart[b * NCHUNK + tid] : 0.f;
#pragma unroll
        for (int o = 16; o; o >>= 1) v += __shfl_xor_sync(0xffffffffu, v, o);
        if (tid == 0) sinv = 1.0f / v;
    }
    __syncthreads();
    float s = 0.f;
#pragma unroll
    for (int c = 0; c < NCHUNK; c++) s += g_partial[(b * NCHUNK + c) * Dn + tid];
    s *= sinv;
    g_sel[b * Dn + tid] = s;
    if (out_sel) out_sel[b * Dn + tid] = s;
}

// ---------------- K4: vocab inner products + exp-sum + target capture ----
// block 128 (4 warps), warp w owns batches 4w..4w+3, sel cached in regs.
__global__ __launch_bounds__(128) void k_ip(
    const float* __restrict__ emb, const int* __restrict__ x,
    const int* __restrict__ mask_idx) {
    int w = threadIdx.x >> 5, lane = threadIdx.x & 31;
    float4 selr[4][4];
    int tgt[4];
#pragma unroll
    for (int bb = 0; bb < 4; bb++) {
        int b = w * 4 + bb;
        const float4* s4 = (const float4*)(g_sel + (size_t)b * Dn);
#pragma unroll
        for (int j = 0; j < 4; j++) selr[bb][j] = s4[lane + 32 * j];
        tgt[bb] = x[b * Ln + mask_idx[b]];
    }
    float es[4] = {0.f, 0.f, 0.f, 0.f};
    int t0 = blockIdx.x * 32;
    for (int ti = 0; ti < 32; ti++) {
        int t = t0 + ti;
        const float4* er = (const float4*)(emb + (size_t)t * Dn);
        float4 e[4];
#pragma unroll
        for (int j = 0; j < 4; j++) e[j] = er[lane + 32 * j];
        float acc[4] = {0.f, 0.f, 0.f, 0.f};
#pragma unroll
        for (int j = 0; j < 4; j++)
#pragma unroll
            for (int bb = 0; bb < 4; bb++)
                acc[bb] += dot4(e[j], selr[bb][j]);
        float sc = g_inv_e[t];
#pragma unroll
        for (int bb = 0; bb < 4; bb++) {
            float v = acc[bb];
#pragma unroll
            for (int o = 16; o; o >>= 1) v += __shfl_xor_sync(0xffffffffu, v, o);
            v *= sc;
            if (lane == 0) {
                es[bb] += __expf(v);
                if (t == tgt[bb]) g_tgtip[w * 4 + bb] = v;
            }
        }
    }
#pragma unroll
    for (int bb = 0; bb < 4; bb++)
        if (lane == 0) g_esum[(w * 4 + bb) * NIPB + blockIdx.x] = es[bb];
}

// ---------------- K5: final loss ----------------
__global__ __launch_bounds__(512) void k_final(float* __restrict__ out_loss) {
    __shared__ float lp[16];
    int w = threadIdx.x >> 5, lane = threadIdx.x & 31;   // 16 warps, warp per b
    float s = 0.f;
    for (int i = lane; i < NIPB; i += 32) s += g_esum[w * NIPB + i];
#pragma unroll
    for (int o = 16; o; o >>= 1) s += __shfl_xor_sync(0xffffffffu, s, o);
    if (lane == 0) lp[w] = g_tgtip[w] - logf(s);
    __syncthreads();
    if (threadIdx.x == 0) {
        float t = 0.f;
#pragma unroll
        for (int b = 0; b < Bn; b++) t += lp[b];
        if (out_loss) *out_loss = -t * (1.0f / Bn);
    }
}

// ---------------- host ----------------
extern "C" void kernel_launch(void* const* d_in, const int* in_sizes, int n_in,
                              void* d_out, int out_size) {
    const int* x = nullptr;
    const int* mask_idx = nullptr;
    const float* emb = nullptr;
    const float* pos = nullptr;
    for (int i = 0; i < n_in; i++) {
        switch (in_sizes[i]) {
            case Bn * Ln:        x = (const int*)d_in[i]; break;
            case Bn:             mask_idx = (const int*)d_in[i]; break;
            case (Mn + 1) * Dn:  emb = (const float*)d_in[i]; break;
            case Ln * Dn:        pos = (const float*)d_in[i]; break;
            default: break;
        }
    }

    float* out = (float*)d_out;
    float* lossp;
    float* selp;
    if (out_size == 1 + Bn * Dn) { lossp = out; selp = out + 1; }
    else if (out_size == Bn * Dn) { lossp = nullptr; selp = out; }
    else if (out_size == 1) { lossp = out; selp = nullptr; }
    else { lossp = out; selp = (out_size > 1) ? out + 1 : nullptr; }

    // K1: all row norms (emb + pos) in one launch
    {
        int totalWarps = (Mn + 1) + Ln;
        int blocks = (totalWarps * 32 + 255) / 256;
        k_norms<<<blocks, 256>>>(emb, pos);
    }
    // K2: fused logits+exp+weighted-sum
    {
        dim3 g(NCHUNK, Bn);
        k24<<<g, 512>>>(emb, pos, x, mask_idx);
    }
    // K3: reduce -> sel_output
    k_sel<<<Bn, 512>>>(selp);
    // K4: vocab inner products + exp-sums + target
    k_ip<<<NIPB, 128>>>(emb, x, mask_idx);
    // K5: final loss
    k_final<<<1, 512>>>(lossp);
}

// round 3
// speedup vs baseline: 1.4619x; 1.4619x over previous
#include <cuda_runtime.h>
#include <math.h>

#define Bn 16
#define Ln 2048
#define Mn 32000
#define Dn 512
#define NCHUNK 16           // chunks per batch in k24 (128 tokens each)
#define NIPB   1000         // k_ip blocks (32 tokens each)

// ---------------- scratch ----------------
__device__ float g_inv_e[Mn + 1];
__device__ float g_inv_p[Ln];
__device__ float g_partial[Bn * NCHUNK * Dn];
__device__ float g_wpart[Bn * NCHUNK];
__device__ float g_sel[Bn * Dn];
__device__ float g_esum[Bn * NIPB];
__device__ float g_tgtip[Bn];

__device__ __forceinline__ float dot4(float4 a, float4 b) {
    return a.x * b.x + a.y * b.y + a.z * b.z + a.w * b.w;
}

// packed 2xfp32 fma: d = a*b + d
#define FMA2(d, a, b) \
    asm("fma.rn.f32x2 %0, %1, %2, %3;" : "=l"(d) : "l"(a), "l"(b), "l"(d))

__device__ __forceinline__ float unpack_add(unsigned long long v) {
    float lo, hi;
    asm("mov.b64 {%0,%1}, %2;" : "=f"(lo), "=f"(hi) : "l"(v));
    return lo + hi;
}

// ---------------- K1: row inverse norms for emb AND pos (warp/row) -------
__global__ void k_norms(const float* __restrict__ emb,
                        const float* __restrict__ pos) {
    int warp = (blockIdx.x * blockDim.x + threadIdx.x) >> 5;
    int lane = threadIdx.x & 31;
    int total = (Mn + 1) + Ln;
    if (warp >= total) return;
    const float* r = (warp <= Mn) ? emb + (size_t)warp * Dn
                                  : pos + (size_t)(warp - (Mn + 1)) * Dn;
    const float4* r4 = (const float4*)r;
    float s = 0.f;
#pragma unroll
    for (int j = 0; j < 4; j++) { float4 v = r4[lane + 32 * j]; s += dot4(v, v); }
#pragma unroll
    for (int o = 16; o; o >>= 1) s += __shfl_xor_sync(0xffffffffu, s, o);
    if (lane == 0) {
        float inv = 1.0f / fmaxf(sqrtf(s), 1.0f);
        if (warp <= Mn) g_inv_e[warp] = inv; else g_inv_p[warp - (Mn + 1)] = inv;
    }
}

// ---------------- K2: fused logits + exp + weighted gather-sum -----------
// grid (NCHUNK, Bn), block 512. Chunk = 128 tokens.
__global__ __launch_bounds__(512) void k24(
    const float* __restrict__ emb, const float* __restrict__ pos,
    const int* __restrict__ x, const int* __restrict__ mask_idx) {
    __shared__ __align__(16) float qs[Dn];
    __shared__ __align__(16) float ps[Dn];
    __shared__ float wsh[128];   // exp(logit)*inv_e[tok]
    __shared__ float esh[128];   // exp(logit)
    __shared__ int   tsh[128];
    __shared__ __align__(16) float4 red4[4][128];
    int b = blockIdx.y, c = blockIdx.x;
    int tid = threadIdx.x;
    int mb = mask_idx[b];
    float ie_m = g_inv_e[Mn];
    float ip_mb = g_inv_p[mb];
    qs[tid] = emb[(size_t)Mn * Dn + tid] * ie_m;
    ps[tid] = pos[(size_t)mb * Dn + tid] * ip_mb;
    __syncthreads();

    int wid = tid >> 5, lane = tid & 31;
    const float4* q4 = (const float4*)qs;
    const float4* p4 = (const float4*)ps;
#pragma unroll 1
    for (int k = 0; k < 8; k++) {
        int i = wid * 8 + k;            // 0..127 in chunk
        int m = c * 128 + i;
        int tok = (m == mb) ? Mn : x[b * Ln + m];
        const float4* er = (const float4*)(emb + (size_t)tok * Dn);
        const float4* pr = (const float4*)(pos + (size_t)m * Dn);
        float dc = 0.f, dp = 0.f;
#pragma unroll
        for (int j = 0; j < 4; j++) {
            dc += dot4(er[lane + 32 * j], q4[lane + 32 * j]);
            dp += dot4(pr[lane + 32 * j], p4[lane + 32 * j]);
        }
        float inve = g_inv_e[tok];
        float s = dc * inve + dp * g_inv_p[m];
#pragma unroll
        for (int o = 16; o; o >>= 1) s += __shfl_xor_sync(0xffffffffu, s, o);
        if (lane == 0) {
            float e = __expf(s * (1.0f / 32.0f));
            esh[i] = e;
            wsh[i] = e * inve;
            tsh[i] = tok;
        }
    }
    __syncthreads();
    // partial sum of exp over this chunk (fixed-order, deterministic)
    if (tid < 32) {
        float sw = esh[tid] + esh[tid + 32] + esh[tid + 64] + esh[tid + 96];
#pragma unroll
        for (int o = 16; o; o >>= 1) sw += __shfl_xor_sync(0xffffffffu, sw, o);
        if (tid == 0) g_wpart[b * NCHUNK + c] = sw;
    }
    // weighted sum over chunk, vectorized: 4 token-groups x 128 float4 lanes
    {
        int g = tid >> 7, l = tid & 127;
        const float4* e4 = (const float4*)emb;
        float4 acc = make_float4(0.f, 0.f, 0.f, 0.f);
#pragma unroll 4
        for (int i = g * 32; i < g * 32 + 32; i++) {
            float w = wsh[i];
            float4 v = e4[(size_t)tsh[i] * 128 + l];
            acc.x += v.x * w; acc.y += v.y * w;
            acc.z += v.z * w; acc.w += v.w * w;
        }
        red4[g][l] = acc;
    }
    __syncthreads();
    if (tid < 128) {
        float4 a0 = red4[0][tid], a1 = red4[1][tid];
        float4 a2 = red4[2][tid], a3 = red4[3][tid];
        float4 s;
        s.x = (a0.x + a1.x) + (a2.x + a3.x);
        s.y = (a0.y + a1.y) + (a2.y + a3.y);
        s.z = (a0.z + a1.z) + (a2.z + a3.z);
        s.w = (a0.w + a1.w) + (a2.w + a3.w);
        ((float4*)g_partial)[(size_t)(b * NCHUNK + c) * 128 + tid] = s;
    }
}

// ---------------- K3: reduce partials, normalize -> sel ----------------
__global__ __launch_bounds__(512) void k_sel(float* __restrict__ out_sel) {
    int b = blockIdx.x, tid = threadIdx.x;
    __shared__ float sinv;
    if (tid < 32) {
        float v = (tid < NCHUNK) ? g_wpart[b * NCHUNK + tid] : 0.f;
#pragma unroll
        for (int o = 16; o; o >>= 1) v += __shfl_xor_sync(0xffffffffu, v, o);
        if (tid == 0) sinv = 1.0f / v;
    }
    __syncthreads();
    float s = 0.f;
#pragma unroll
    for (int c = 0; c < NCHUNK; c++) s += g_partial[(b * NCHUNK + c) * Dn + tid];
    s *= sinv;
    g_sel[b * Dn + tid] = s;
    if (out_sel) out_sel[b * Dn + tid] = s;
}

// ---------------- K4: vocab inner products + exp-sum + target capture ----
// block 128 (4 warps), warp w owns batches 4w..4w+3 (sel packed in regs).
// Per token: f32x2 FMAs, 6-shuffle multi-value butterfly, parallel expf.
__global__ __launch_bounds__(128) void k_ip(
    const float* __restrict__ emb, const int* __restrict__ x,
    const int* __restrict__ mask_idx) {
    int w = threadIdx.x >> 5, lane = threadIdx.x & 31;
    // batch owned by this lane after the butterfly
    int bl = ((lane & 1) ? 2 : 0) | ((lane & 2) ? 1 : 0);
    int myb = w * 4 + bl;
    int mytgt = x[myb * Ln + mask_idx[myb]];

    unsigned long long selp[4][8];
#pragma unroll
    for (int bb = 0; bb < 4; bb++) {
        const ulonglong2* s2 = (const ulonglong2*)(g_sel + (size_t)(w * 4 + bb) * Dn);
#pragma unroll
        for (int j = 0; j < 4; j++) {
            ulonglong2 q = s2[lane + 32 * j];
            selp[bb][2 * j] = q.x;
            selp[bb][2 * j + 1] = q.y;
        }
    }

    float es = 0.f;
    float tv = 0.f;
    int found = 0;
    int t0 = blockIdx.x * 32;
#pragma unroll 1
    for (int ti = 0; ti < 32; ti++) {
        int t = t0 + ti;
        const ulonglong2* e2 = (const ulonglong2*)(emb + (size_t)t * Dn);
        unsigned long long ep[8];
#pragma unroll
        for (int j = 0; j < 4; j++) {
            ulonglong2 q = e2[lane + 32 * j];
            ep[2 * j] = q.x;
            ep[2 * j + 1] = q.y;
        }
        unsigned long long acc2[4] = {0ull, 0ull, 0ull, 0ull};
#pragma unroll
        for (int j = 0; j < 8; j++) {
            FMA2(acc2[0], ep[j], selp[0][j]);
            FMA2(acc2[1], ep[j], selp[1][j]);
            FMA2(acc2[2], ep[j], selp[2][j]);
            FMA2(acc2[3], ep[j], selp[3][j]);
        }
        float a0 = unpack_add(acc2[0]);
        float a1 = unpack_add(acc2[1]);
        float a2 = unpack_add(acc2[2]);
        float a3 = unpack_add(acc2[3]);
        // step 0 (xor 1): lower lanes keep {b0,b1}, upper keep {b2,b3}
        {
            int up = lane & 1;
            float s0 = up ? a0 : a2;
            float s1 = up ? a1 : a3;
            float r0 = __shfl_xor_sync(0xffffffffu, s0, 1);
            float r1 = __shfl_xor_sync(0xffffffffu, s1, 1);
            float n0 = (up ? a2 : a0) + r0;
            float n1 = (up ? a3 : a1) + r1;
            a0 = n0; a1 = n1;
        }
        // step 1 (xor 2): keep one value
        {
            int up = lane & 2;
            float s0 = up ? a0 : a1;
            float r0 = __shfl_xor_sync(0xffffffffu, s0, 2);
            a0 = (up ? a1 : a0) + r0;
        }
        // full butterflies over remaining lane bits
        a0 += __shfl_xor_sync(0xffffffffu, a0, 4);
        a0 += __shfl_xor_sync(0xffffffffu, a0, 8);
        a0 += __shfl_xor_sync(0xffffffffu, a0, 16);
        // every lane now holds the full dot for batch myb
        float v = a0 * g_inv_e[t];
        es += __expf(v);
        if (t == mytgt) { tv = v; found = 1; }
    }
    if (lane < 4) {
        g_esum[myb * NIPB + blockIdx.x] = es;
        if (found) g_tgtip[myb] = tv;
    }
}

// ---------------- K5: final loss ----------------
__global__ __launch_bounds__(512) void k_final(float* __restrict__ out_loss) {
    __shared__ float lp[16];
    int w = threadIdx.x >> 5, lane = threadIdx.x & 31;   // 16 warps, warp per b
    float s = 0.f;
    for (int i = lane; i < NIPB; i += 32) s += g_esum[w * NIPB + i];
#pragma unroll
    for (int o = 16; o; o >>= 1) s += __shfl_xor_sync(0xffffffffu, s, o);
    if (lane == 0) lp[w] = g_tgtip[w] - logf(s);
    __syncthreads();
    if (threadIdx.x == 0) {
        float t = 0.f;
#pragma unroll
        for (int b = 0; b < Bn; b++) t += lp[b];
        if (out_loss) *out_loss = -t * (1.0f / Bn);
    }
}

// ---------------- host ----------------
extern "C" void kernel_launch(void* const* d_in, const int* in_sizes, int n_in,
                              void* d_out, int out_size) {
    const int* x = nullptr;
    const int* mask_idx = nullptr;
    const float* emb = nullptr;
    const float* pos = nullptr;
    for (int i = 0; i < n_in; i++) {
        switch (in_sizes[i]) {
            case Bn * Ln:        x = (const int*)d_in[i]; break;
            case Bn:             mask_idx = (const int*)d_in[i]; break;
            case (Mn + 1) * Dn:  emb = (const float*)d_in[i]; break;
            case Ln * Dn:        pos = (const float*)d_in[i]; break;
            default: break;
        }
    }

    float* out = (float*)d_out;
    float* lossp;
    float* selp;
    if (out_size == 1 + Bn * Dn) { lossp = out; selp = out + 1; }
    else if (out_size == Bn * Dn) { lossp = nullptr; selp = out; }
    else if (out_size == 1) { lossp = out; selp = nullptr; }
    else { lossp = out; selp = (out_size > 1) ? out + 1 : nullptr; }

    // K1: all row norms (emb + pos) in one launch
    {
        int totalWarps = (Mn + 1) + Ln;
        int blocks = (totalWarps * 32 + 255) / 256;
        k_norms<<<blocks, 256>>>(emb, pos);
    }
    // K2: fused logits+exp+weighted-sum
    {
        dim3 g(NCHUNK, Bn);
        k24<<<g, 512>>>(emb, pos, x, mask_idx);
    }
    // K3: reduce -> sel_output
    k_sel<<<Bn, 512>>>(selp);
    // K4: vocab inner products + exp-sums + target
    k_ip<<<NIPB, 128>>>(emb, x, mask_idx);
    // K5: final loss
    k_final<<<1, 512>>>(lossp);
}

// round 4
// speedup vs baseline: 1.8995x; 1.2993x over previous
#include <cuda_runtime.h>
#include <math.h>

#define Bn 16
#define Ln 2048
#define Mn 32000
#define Dn 512
#define NCHUNK 16           // chunks per batch in k24 (128 tokens each)
#define NIPB   1000         // k_ip blocks (32 tokens each)
#define PSTRIDE 36          // padded floats per (b,t) partial row
#define IP_SMEM (Bn * 32 * PSTRIDE * 4)   // 73728 bytes

// ---------------- scratch ----------------
__device__ float g_inv_e[Mn + 1];
__device__ float g_inv_p[Ln];
__device__ float g_partial[Bn * NCHUNK * Dn];
__device__ float g_wpart[Bn * NCHUNK];
__device__ float g_sel[Bn * Dn];
__device__ float g_esum[Bn * NIPB];
__device__ float g_tgtip[Bn];

__device__ __forceinline__ float dot4(float4 a, float4 b) {
    return a.x * b.x + a.y * b.y + a.z * b.z + a.w * b.w;
}

// packed 2xfp32 fma: d = a*b + d
#define FMA2(d, a, b) \
    asm("fma.rn.f32x2 %0, %1, %2, %3;" : "=l"(d) : "l"(a), "l"(b), "l"(d))

__device__ __forceinline__ float unpack_add(unsigned long long v) {
    float lo, hi;
    asm("mov.b64 {%0,%1}, %2;" : "=f"(lo), "=f"(hi) : "l"(v));
    return lo + hi;
}

// ---------------- K1: row inverse norms for emb AND pos (warp/row) -------
__global__ void k_norms(const float* __restrict__ emb,
                        const float* __restrict__ pos) {
    int warp = (blockIdx.x * blockDim.x + threadIdx.x) >> 5;
    int lane = threadIdx.x & 31;
    int total = (Mn + 1) + Ln;
    if (warp >= total) return;
    const float* r = (warp <= Mn) ? emb + (size_t)warp * Dn
                                  : pos + (size_t)(warp - (Mn + 1)) * Dn;
    const float4* r4 = (const float4*)r;
    float s = 0.f;
#pragma unroll
    for (int j = 0; j < 4; j++) { float4 v = r4[lane + 32 * j]; s += dot4(v, v); }
#pragma unroll
    for (int o = 16; o; o >>= 1) s += __shfl_xor_sync(0xffffffffu, s, o);
    if (lane == 0) {
        float inv = 1.0f / fmaxf(sqrtf(s), 1.0f);
        if (warp <= Mn) g_inv_e[warp] = inv; else g_inv_p[warp - (Mn + 1)] = inv;
    }
}

// ---------------- K2: fused logits + exp + weighted gather-sum -----------
// grid (NCHUNK, Bn), block 512. Chunk = 128 tokens.
__global__ __launch_bounds__(512) void k24(
    const float* __restrict__ emb, const float* __restrict__ pos,
    const int* __restrict__ x, const int* __restrict__ mask_idx) {
    __shared__ __align__(16) float qs[Dn];
    __shared__ __align__(16) float ps[Dn];
    __shared__ float wsh[128];   // exp(logit)*inv_e[tok]
    __shared__ float esh[128];   // exp(logit)
    __shared__ int   tsh[128];
    __shared__ __align__(16) float4 red4[4][128];
    int b = blockIdx.y, c = blockIdx.x;
    int tid = threadIdx.x;
    int mb = mask_idx[b];
    float ie_m = g_inv_e[Mn];
    float ip_mb = g_inv_p[mb];
    qs[tid] = emb[(size_t)Mn * Dn + tid] * ie_m;
    ps[tid] = pos[(size_t)mb * Dn + tid] * ip_mb;
    __syncthreads();

    int wid = tid >> 5, lane = tid & 31;
    const float4* q4 = (const float4*)qs;
    const float4* p4 = (const float4*)ps;
#pragma unroll 1
    for (int k = 0; k < 8; k++) {
        int i = wid * 8 + k;            // 0..127 in chunk
        int m = c * 128 + i;
        int tok = (m == mb) ? Mn : x[b * Ln + m];
        const float4* er = (const float4*)(emb + (size_t)tok * Dn);
        const float4* pr = (const float4*)(pos + (size_t)m * Dn);
        float dc = 0.f, dp = 0.f;
#pragma unroll
        for (int j = 0; j < 4; j++) {
            dc += dot4(er[lane + 32 * j], q4[lane + 32 * j]);
            dp += dot4(pr[lane + 32 * j], p4[lane + 32 * j]);
        }
        float inve = g_inv_e[tok];
        float s = dc * inve + dp * g_inv_p[m];
#pragma unroll
        for (int o = 16; o; o >>= 1) s += __shfl_xor_sync(0xffffffffu, s, o);
        if (lane == 0) {
            float e = __expf(s * (1.0f / 32.0f));
            esh[i] = e;
            wsh[i] = e * inve;
            tsh[i] = tok;
        }
    }
    __syncthreads();
    // partial sum of exp over this chunk (fixed-order, deterministic)
    if (tid < 32) {
        float sw = esh[tid] + esh[tid + 32] + esh[tid + 64] + esh[tid + 96];
#pragma unroll
        for (int o = 16; o; o >>= 1) sw += __shfl_xor_sync(0xffffffffu, sw, o);
        if (tid == 0) g_wpart[b * NCHUNK + c] = sw;
    }
    // weighted sum over chunk, vectorized: 4 token-groups x 128 float4 lanes
    {
        int g = tid >> 7, l = tid & 127;
        const float4* e4 = (const float4*)emb;
        float4 acc = make_float4(0.f, 0.f, 0.f, 0.f);
#pragma unroll 4
        for (int i = g * 32; i < g * 32 + 32; i++) {
            float w = wsh[i];
            float4 v = e4[(size_t)tsh[i] * 128 + l];
            acc.x += v.x * w; acc.y += v.y * w;
            acc.z += v.z * w; acc.w += v.w * w;
        }
        red4[g][l] = acc;
    }
    __syncthreads();
    if (tid < 128) {
        float4 a0 = red4[0][tid], a1 = red4[1][tid];
        float4 a2 = red4[2][tid], a3 = red4[3][tid];
        float4 s;
        s.x = (a0.x + a1.x) + (a2.x + a3.x);
        s.y = (a0.y + a1.y) + (a2.y + a3.y);
        s.z = (a0.z + a1.z) + (a2.z + a3.z);
        s.w = (a0.w + a1.w) + (a2.w + a3.w);
        ((float4*)g_partial)[(size_t)(b * NCHUNK + c) * 128 + tid] = s;
    }
}

// ---------------- K3: reduce partials, normalize -> sel ----------------
__global__ __launch_bounds__(512) void k_sel(float* __restrict__ out_sel) {
    int b = blockIdx.x, tid = threadIdx.x;
    __shared__ float sinv;
    if (tid < 32) {
        float v = (tid < NCHUNK) ? g_wpart[b * NCHUNK + tid] : 0.f;
#pragma unroll
        for (int o = 16; o; o >>= 1) v += __shfl_xor_sync(0xffffffffu, v, o);
        if (tid == 0) sinv = 1.0f / v;
    }
    __syncthreads();
    float s = 0.f;
#pragma unroll
    for (int c = 0; c < NCHUNK; c++) s += g_partial[(b * NCHUNK + c) * Dn + tid];
    s *= sinv;
    g_sel[b * Dn + tid] = s;
    if (out_sel) out_sel[b * Dn + tid] = s;
}

// ---------------- K4: vocab inner products, 2-phase, no inner shuffles ---
// block 128 (4 warps). Phase 1: warp w computes within-lane partial dots for
// batches 4w..4w+3 over 32 tokens (pure streaming, double-buffered loads),
// storing one float per (b,t,lane) in smem. Phase 2: tree-sum partials,
// scale, exp, one butterfly per batch.
__device__ __forceinline__ void ld_row(unsigned long long* ep,
                                       const ulonglong2* e2, int lane) {
#pragma unroll
    for (int j = 0; j < 4; j++) {
        ulonglong2 q = e2[lane + 32 * j];
        ep[2 * j] = q.x;
        ep[2 * j + 1] = q.y;
    }
}

__device__ __forceinline__ void comp_store(
    const unsigned long long ep[8], const unsigned long long selp[4][8],
    float* part, int b0, int t, int lane) {
    unsigned long long acc2[4] = {0ull, 0ull, 0ull, 0ull};
#pragma unroll
    for (int j = 0; j < 8; j++) {
        FMA2(acc2[0], ep[j], selp[0][j]);
        FMA2(acc2[1], ep[j], selp[1][j]);
        FMA2(acc2[2], ep[j], selp[2][j]);
        FMA2(acc2[3], ep[j], selp[3][j]);
    }
#pragma unroll
    for (int bb = 0; bb < 4; bb++)
        part[((b0 + bb) * 32 + t) * PSTRIDE + lane] = unpack_add(acc2[bb]);
}

__global__ __launch_bounds__(128, 3) void k_ip(
    const float* __restrict__ emb, const int* __restrict__ x,
    const int* __restrict__ mask_idx) {
    extern __shared__ float part[];   // [Bn][32][PSTRIDE]
    int w = threadIdx.x >> 5, lane = threadIdx.x & 31;
    int b0 = w * 4;
    int t0 = blockIdx.x * 32;

    unsigned long long selp[4][8];
#pragma unroll
    for (int bb = 0; bb < 4; bb++) {
        const ulonglong2* s2 = (const ulonglong2*)(g_sel + (size_t)(b0 + bb) * Dn);
#pragma unroll
        for (int j = 0; j < 4; j++) {
            ulonglong2 q = s2[lane + 32 * j];
            selp[bb][2 * j] = q.x;
            selp[bb][2 * j + 1] = q.y;
        }
    }

    const ulonglong2* e2 = (const ulonglong2*)(emb + (size_t)t0 * Dn);
    unsigned long long epA[8], epB[8];
    ld_row(epA, e2, lane);
#pragma unroll 4
    for (int t = 0; t < 32; t += 2) {
        ld_row(epB, e2 + (size_t)(t + 1) * 128, lane);
        comp_store(epA, selp, part, b0, t, lane);
        if (t + 2 < 32) ld_row(epA, e2 + (size_t)(t + 2) * 128, lane);
        comp_store(epB, selp, part, b0, t + 1, lane);
    }
    __syncthreads();

    // Phase 2: warp w handles batches w, w+4, w+8, w+12; lane = token.
#pragma unroll
    for (int k = 0; k < 4; k++) {
        int b = w + 4 * k;
        const float4* row = (const float4*)&part[(b * 32 + lane) * PSTRIDE];
        float4 s0 = row[0], s1 = row[1], s2 = row[2], s3 = row[3];
        float4 s4 = row[4], s5 = row[5], s6 = row[6], s7 = row[7];
        float4 u;
        u.x = (s0.x + s1.x) + (s2.x + s3.x) + ((s4.x + s5.x) + (s6.x + s7.x));
        u.y = (s0.y + s1.y) + (s2.y + s3.y) + ((s4.y + s5.y) + (s6.y + s7.y));
        u.z = (s0.z + s1.z) + (s2.z + s3.z) + ((s4.z + s5.z) + (s6.z + s7.z));
        u.w = (s0.w + s1.w) + (s2.w + s3.w) + ((s4.w + s5.w) + (s6.w + s7.w));
        float dot = (u.x + u.y) + (u.z + u.w);
        int tok = t0 + lane;
        float v = dot * g_inv_e[tok];
        int tgt = x[b * Ln + mask_idx[b]];
        if (tok == tgt) g_tgtip[b] = v;
        float e = __expf(v);
#pragma unroll
        for (int o = 16; o; o >>= 1) e += __shfl_xor_sync(0xffffffffu, e, o);
        if (lane == 0) g_esum[b * NIPB + blockIdx.x] = e;
    }
}

// ---------------- K5: final loss ----------------
__global__ __launch_bounds__(512) void k_final(float* __restrict__ out_loss) {
    __shared__ float lp[16];
    int w = threadIdx.x >> 5, lane = threadIdx.x & 31;   // 16 warps, warp per b
    float s = 0.f;
    for (int i = lane; i < NIPB; i += 32) s += g_esum[w * NIPB + i];
#pragma unroll
    for (int o = 16; o; o >>= 1) s += __shfl_xor_sync(0xffffffffu, s, o);
    if (lane == 0) lp[w] = g_tgtip[w] - logf(s);
    __syncthreads();
    if (threadIdx.x == 0) {
        float t = 0.f;
#pragma unroll
        for (int b = 0; b < Bn; b++) t += lp[b];
        if (out_loss) *out_loss = -t * (1.0f / Bn);
    }
}

// ---------------- host ----------------
extern "C" void kernel_launch(void* const* d_in, const int* in_sizes, int n_in,
                              void* d_out, int out_size) {
    const int* x = nullptr;
    const int* mask_idx = nullptr;
    const float* emb = nullptr;
    const float* pos = nullptr;
    for (int i = 0; i < n_in; i++) {
        switch (in_sizes[i]) {
            case Bn * Ln:        x = (const int*)d_in[i]; break;
            case Bn:             mask_idx = (const int*)d_in[i]; break;
            case (Mn + 1) * Dn:  emb = (const float*)d_in[i]; break;
            case Ln * Dn:        pos = (const float*)d_in[i]; break;
            default: break;
        }
    }

    float* out = (float*)d_out;
    float* lossp;
    float* selp;
    if (out_size == 1 + Bn * Dn) { lossp = out; selp = out + 1; }
    else if (out_size == Bn * Dn) { lossp = nullptr; selp = out; }
    else if (out_size == 1) { lossp = out; selp = nullptr; }
    else { lossp = out; selp = (out_size > 1) ? out + 1 : nullptr; }

    static int smem_set = 0;
    if (!smem_set) {
        cudaFuncSetAttribute(k_ip, cudaFuncAttributeMaxDynamicSharedMemorySize,
                             IP_SMEM);
        smem_set = 1;
    }

    // K1: all row norms (emb + pos) in one launch
    {
        int totalWarps = (Mn + 1) + Ln;
        int blocks = (totalWarps * 32 + 255) / 256;
        k_norms<<<blocks, 256>>>(emb, pos);
    }
    // K2: fused logits+exp+weighted-sum
    {
        dim3 g(NCHUNK, Bn);
        k24<<<g, 512>>>(emb, pos, x, mask_idx);
    }
    // K3: reduce -> sel_output
    k_sel<<<Bn, 512>>>(selp);
    // K4: vocab inner products + exp-sums + target
    k_ip<<<NIPB, 128, IP_SMEM>>>(emb, x, mask_idx);
    // K5: final loss
    k_final<<<1, 512>>>(lossp);
}